// round 5
// baseline (speedup 1.0000x reference)
#include <cuda_runtime.h>
#include <cstdint>

#define Bdim 256
#define Udim 512
#define Ddim 512
#define N4U  2048

typedef unsigned long long ull;

// ---------------- scratch ----------------
__device__ float g_pre [Bdim * N4U];        // gates pre-activations [B, 4U]
__device__ float g_hw  [Bdim * Udim];       // h_tm1 @ w
__device__ float g_red8[Bdim * 8 * Udim];   // partial hebb reductions (8 u-chunks)
__device__ float g_g   [Bdim * Udim];       // eta[b,v]*itc[b,v]

// ---------------- packed f32x2 helpers ----------------
__device__ __forceinline__ ull pk2(float x, float y) {
    ull r; asm("mov.b64 %0, {%1, %2};" : "=l"(r) : "f"(x), "f"(y)); return r;
}
__device__ __forceinline__ ull fma2(ull a, ull b, ull c) {
    ull d; asm("fma.rn.f32x2 %0, %1, %2, %3;" : "=l"(d) : "l"(a), "l"(b), "l"(c)); return d;
}
__device__ __forceinline__ float2 upk(ull v) {
    float2 r; asm("mov.b64 {%0, %1}, %2;" : "=f"(r.x), "=f"(r.y) : "l"(v)); return r;
}

// =======================================================================
// Phase 1: one kernel, GEMM blocks first (co-reside with DRAM-bound reduce)
//   [0, 256)     : gates GEMM, 32x64 tiles
//   [256, 320)   : hw GEMM,    32x64 tiles
//   [320, 2368)  : hebb partial reduce (b = t>>3, 64-u chunk = t&7)
// =======================================================================

__device__ __forceinline__ void gemm32x64(
    const float* __restrict__ A1, const float* __restrict__ B1,
    const float* __restrict__ A2, const float* __restrict__ B2,
    const float* __restrict__ bias, float* __restrict__ C,
    int N, int m0, int n0, bool do_rec, bool add_bias, float* smem)
{
    const int K = 512;
    float (*As)[32] = (float(*)[32])smem;         // 16 x 32
    float (*Bs)[64] = (float(*)[64])(smem + 512); // 16 x 64

    int tid = threadIdx.x;
    int tx  = tid & 15;
    int ty  = tid >> 4;

    ull acc[2][2];
    acc[0][0] = acc[0][1] = acc[1][0] = acc[1][1] = 0ull;

    int npass = do_rec ? 2 : 1;
    for (int pass = 0; pass < npass; ++pass) {
        const float* A = pass ? A2 : A1;   // [256, 512] ld 512
        const float* B = pass ? B2 : B1;   // [512, N]   ld N
        for (int k0 = 0; k0 < K; k0 += 16) {
            #pragma unroll
            for (int t = 0; t < 2; ++t) {
                int i = tid + t * 256;
                As[i & 15][i >> 4] = A[(m0 + (i >> 4)) * K + k0 + (i & 15)];
            }
            #pragma unroll
            for (int t = 0; t < 4; ++t) {
                int i = tid + t * 256;
                Bs[i >> 6][i & 63] = B[(k0 + (i >> 6)) * N + n0 + (i & 63)];
            }
            __syncthreads();
            #pragma unroll
            for (int kk = 0; kk < 16; ++kk) {
                float2 av = *(const float2*)&As[kk][ty * 2];
                ulonglong2 bv = *(const ulonglong2*)&Bs[kk][tx * 4];
                ull a0 = pk2(av.x, av.x);
                ull a1 = pk2(av.y, av.y);
                acc[0][0] = fma2(a0, bv.x, acc[0][0]);
                acc[0][1] = fma2(a0, bv.y, acc[0][1]);
                acc[1][0] = fma2(a1, bv.x, acc[1][0]);
                acc[1][1] = fma2(a1, bv.y, acc[1][1]);
            }
            __syncthreads();
        }
    }

    int n = n0 + tx * 4;
    float b0 = 0.f, b1 = 0.f, b2 = 0.f, b3 = 0.f;
    if (add_bias) { b0 = bias[n]; b1 = bias[n+1]; b2 = bias[n+2]; b3 = bias[n+3]; }
    #pragma unroll
    for (int r = 0; r < 2; ++r) {
        int m = m0 + ty * 2 + r;
        float2 lo = upk(acc[r][0]);
        float2 hi = upk(acc[r][1]);
        float4 o = make_float4(lo.x + b0, lo.y + b1, hi.x + b2, hi.y + b3);
        *(float4*)&C[m * N + n] = o;
    }
}

__global__ void __launch_bounds__(256) phase1_kernel(
    const float* __restrict__ x,     const float* __restrict__ kernel,
    const float* __restrict__ h_tm1, const float* __restrict__ rec,
    const float* __restrict__ bias,  const float* __restrict__ w,
    const float* __restrict__ hebb,
    float* __restrict__ pre, float* __restrict__ hw, float* __restrict__ red8)
{
    __shared__ __align__(16) float smem[1536];   // 6KB
    int bid = blockIdx.x;
    int tid = threadIdx.x;

    if (bid < 256) {
        int n0 = (bid & 31) * 64;
        int m0 = (bid >> 5) * 32;
        bool do_rec = !(n0 >= 2 * Udim && n0 < 3 * Udim);  // c-slice: no rec
        gemm32x64(x, kernel, h_tm1, rec, bias, pre, N4U, m0, n0, do_rec, true, smem);
    } else if (bid < 320) {
        int t  = bid - 256;
        int n0 = (t & 7) * 64;
        int m0 = (t >> 3) * 32;
        gemm32x64(h_tm1, w, nullptr, nullptr, nullptr, hw, Udim, m0, n0, false, false, smem);
    } else {
        // ---- hebb partial reduce: red8[b,chunk,v] = sum over 64 u's ----
        // 4 independent u-streams per thread (update-kernel-style MLP).
        int t     = bid - 320;       // 0..2047
        int b     = t >> 3;
        int chunk = t & 7;           // 64-u chunk
        int v4    = tid & 127;       // f4 column (512 floats = 128 f4)
        int uh    = tid >> 7;        // 0/1: 32-u half

        ull* hs2 = (ull*)smem;       // 64 duplicated h values (512B)
        if (tid < 64) {
            float hv = h_tm1[b * Udim + chunk * 64 + tid];
            hs2[tid] = pk2(hv, hv);
        }
        __syncthreads();

        const float4* p = (const float4*)(hebb
            + (size_t)b * Udim * Udim
            + (size_t)(chunk * 64 + uh * 32) * Udim) + v4;
        const ull* hb = hs2 + uh * 32;

        // 4 independent streams: stream s covers u = s*8 + i, i = 0..7
        ull a0x = 0, a0y = 0, a1x = 0, a1y = 0;
        ull a2x = 0, a2y = 0, a3x = 0, a3y = 0;
        #pragma unroll
        for (int i = 0; i < 8; ++i) {
            float4 l0 = __ldcs(p + (size_t)(i)      * 128);
            float4 l1 = __ldcs(p + (size_t)(i + 8)  * 128);
            float4 l2 = __ldcs(p + (size_t)(i + 16) * 128);
            float4 l3 = __ldcs(p + (size_t)(i + 24) * 128);
            ull h0 = hb[i], h1 = hb[i + 8], h2 = hb[i + 16], h3 = hb[i + 24];
            ulonglong2 v0 = *(ulonglong2*)&l0;
            ulonglong2 v1 = *(ulonglong2*)&l1;
            ulonglong2 v2 = *(ulonglong2*)&l2;
            ulonglong2 v3 = *(ulonglong2*)&l3;
            a0x = fma2(h0, v0.x, a0x);  a0y = fma2(h0, v0.y, a0y);
            a1x = fma2(h1, v1.x, a1x);  a1y = fma2(h1, v1.y, a1y);
            a2x = fma2(h2, v2.x, a2x);  a2y = fma2(h2, v2.y, a2y);
            a3x = fma2(h3, v3.x, a3x);  a3y = fma2(h3, v3.y, a3y);
        }
        // combine the 4 streams
        float2 s0 = upk(a0x), s1 = upk(a1x), s2 = upk(a2x), s3 = upk(a3x);
        float2 t0 = upk(a0y), t1 = upk(a1y), t2 = upk(a2y), t3 = upk(a3y);
        float4 acc = make_float4((s0.x + s1.x) + (s2.x + s3.x),
                                 (s0.y + s1.y) + (s2.y + s3.y),
                                 (t0.x + t1.x) + (t2.x + t3.x),
                                 (t0.y + t1.y) + (t2.y + t3.y));

        __syncthreads();
        float4* st = (float4*)(smem + 128);
        if (uh == 1) st[v4] = acc;
        __syncthreads();
        if (uh == 0) {
            float4 o = st[v4];
            acc.x += o.x; acc.y += o.y; acc.z += o.z; acc.w += o.w;
            ((float4*)(red8 + (size_t)(b * 8 + chunk) * Udim))[v4] = acc;
        }
    }
}

// =======================================================================
// Phase 2: combine — gates, c, h, eta reduction, g   (256 blocks x 512)
// =======================================================================
__device__ __forceinline__ float hsig(float z) {
    return fminf(fmaxf(0.2f * z + 0.5f, 0.f), 1.f);
}

__global__ void __launch_bounds__(512) combine_kernel(
    const float* __restrict__ pre, const float* __restrict__ hw,
    const float* __restrict__ red8, const float* __restrict__ c_tm1,
    const float* __restrict__ alpha, const float* __restrict__ h2mod,
    const float* __restrict__ fanout,
    float* __restrict__ out, float* __restrict__ g)
{
    int b = blockIdx.x;
    int v = threadIdx.x;

    const float* r = red8 + (size_t)b * 8 * Udim;
    float red = ((r[v] + r[Udim + v]) + (r[2 * Udim + v] + r[3 * Udim + v]))
              + ((r[4 * Udim + v] + r[5 * Udim + v]) + (r[6 * Udim + v] + r[7 * Udim + v]));

    float xi = pre[b * N4U + v];
    float xf = pre[b * N4U + Udim + v];
    float xc = pre[b * N4U + 2 * Udim + v];
    float xo = pre[b * N4U + 3 * Udim + v];

    float gi = hsig(xi), gf = hsig(xf), go = hsig(xo);
    float itc = tanhf(xc + hw[b * Udim + v] + alpha[v] * red);
    float c = gf * c_tm1[b * Udim + v] + gi * itc;
    float h = go * tanhf(c);

    out[b * Udim + v] = h;
    out[Bdim * Udim + b * Udim + v] = c;

    float s = h * h2mod[v];
    #pragma unroll
    for (int o = 16; o > 0; o >>= 1) s += __shfl_down_sync(0xffffffffu, s, o);
    __shared__ float ws[16];
    __shared__ float eta_s;
    if ((v & 31) == 0) ws[v >> 5] = s;
    __syncthreads();
    if (v < 16) {
        float t = ws[v];
        #pragma unroll
        for (int o = 8; o > 0; o >>= 1) t += __shfl_down_sync(0xffffu, t, o);
        if (v == 0) eta_s = tanhf(t);
    }
    __syncthreads();
    g[b * Udim + v] = eta_s * fanout[v] * itc;
}

// =======================================================================
// Phase 3: hebb update — 4 independent float4 per thread, streaming hints
// =======================================================================
__global__ void __launch_bounds__(256) hebb_update(
    const float* __restrict__ hebb, const float* __restrict__ h_tm1,
    const float* __restrict__ g, float* __restrict__ out)
{
    int base = blockIdx.x * 1024 + threadIdx.x;

    #pragma unroll
    for (int k = 0; k < 4; ++k) {
        int idx = base + k * 256;
        int row = idx >> 7;            // b*512 + u
        int v4  = idx & 127;
        int b   = idx >> 16;

        float hu = h_tm1[row];
        float4 hv = __ldcs(((const float4*)hebb) + idx);
        float4 gg = ((const float4*)(g + b * Udim))[v4];

        float4 r;
        r.x = fminf(fmaxf(hv.x + hu * gg.x, -2.f), 2.f);
        r.y = fminf(fmaxf(hv.y + hu * gg.y, -2.f), 2.f);
        r.z = fminf(fmaxf(hv.z + hu * gg.z, -2.f), 2.f);
        r.w = fminf(fmaxf(hv.w + hu * gg.w, -2.f), 2.f);
        __stcs(((float4*)out) + idx, r);
    }
}

// ---------------- launch ----------------
extern "C" void kernel_launch(void* const* d_in, const int* in_sizes, int n_in,
                              void* d_out, int out_size)
{
    const float* x      = (const float*)d_in[0];
    const float* h_tm1  = (const float*)d_in[1];
    const float* c_tm1  = (const float*)d_in[2];
    const float* hebb   = (const float*)d_in[3];
    const float* kernel = (const float*)d_in[4];
    const float* rec    = (const float*)d_in[5];
    const float* bias   = (const float*)d_in[6];
    const float* w      = (const float*)d_in[7];
    const float* alpha  = (const float*)d_in[8];
    const float* h2mod  = (const float*)d_in[9];
    const float* fanout = (const float*)d_in[10];
    float* out = (float*)d_out;

    float *pre, *hw, *red8, *gg;
    cudaGetSymbolAddress((void**)&pre,  g_pre);
    cudaGetSymbolAddress((void**)&hw,   g_hw);
    cudaGetSymbolAddress((void**)&red8, g_red8);
    cudaGetSymbolAddress((void**)&gg,   g_g);

    phase1_kernel<<<320 + 2048, 256>>>(x, kernel, h_tm1, rec, bias, w, hebb,
                                       pre, hw, red8);
    combine_kernel<<<Bdim, Udim>>>(pre, hw, red8, c_tm1, alpha, h2mod, fanout, out, gg);
    hebb_update<<<16384, 256>>>(hebb, h_tm1, gg, out + 2 * Bdim * Udim);
}

// round 6
// speedup vs baseline: 1.0071x; 1.0071x over previous
#include <cuda_runtime.h>
#include <cstdint>

#define Bdim 256
#define Udim 512
#define Ddim 512
#define N4U  2048

typedef unsigned long long ull;

// ---------------- scratch ----------------
__device__ float g_pre  [Bdim * N4U];         // gates pre-activations [B, 4U]
__device__ float g_hw   [Bdim * Udim];        // h_tm1 @ w
__device__ float g_red16[Bdim * 16 * Udim];   // partial hebb reductions (16 u-chunks)
__device__ float g_g    [Bdim * Udim];        // eta[b,v]*itc[b,v]

// ---------------- packed f32x2 helpers ----------------
__device__ __forceinline__ ull pk2(float x, float y) {
    ull r; asm("mov.b64 %0, {%1, %2};" : "=l"(r) : "f"(x), "f"(y)); return r;
}
__device__ __forceinline__ ull fma2(ull a, ull b, ull c) {
    ull d; asm("fma.rn.f32x2 %0, %1, %2, %3;" : "=l"(d) : "l"(a), "l"(b), "l"(c)); return d;
}
__device__ __forceinline__ float2 upk(ull v) {
    float2 r; asm("mov.b64 {%0, %1}, %2;" : "=f"(r.x), "=f"(r.y) : "l"(v)); return r;
}

// =======================================================================
// Phase 1: one kernel, GEMM blocks first (co-reside with DRAM-bound reduce)
//   [0, 256)     : gates GEMM, 32x64 tiles
//   [256, 320)   : hw GEMM,    32x64 tiles
//   [320, 4416)  : hebb partial reduce (b = t>>4, 32-u chunk = t&15)
// =======================================================================

__device__ __forceinline__ void gemm32x64(
    const float* __restrict__ A1, const float* __restrict__ B1,
    const float* __restrict__ A2, const float* __restrict__ B2,
    const float* __restrict__ bias, float* __restrict__ C,
    int N, int m0, int n0, bool do_rec, bool add_bias, float* smem)
{
    const int K = 512;
    float (*As)[32] = (float(*)[32])smem;         // 16 x 32
    float (*Bs)[64] = (float(*)[64])(smem + 512); // 16 x 64

    int tid = threadIdx.x;
    int tx  = tid & 15;
    int ty  = tid >> 4;

    ull acc[2][2];
    acc[0][0] = acc[0][1] = acc[1][0] = acc[1][1] = 0ull;

    int npass = do_rec ? 2 : 1;
    for (int pass = 0; pass < npass; ++pass) {
        const float* A = pass ? A2 : A1;   // [256, 512] ld 512
        const float* B = pass ? B2 : B1;   // [512, N]   ld N
        for (int k0 = 0; k0 < K; k0 += 16) {
            #pragma unroll
            for (int t = 0; t < 2; ++t) {
                int i = tid + t * 256;
                As[i & 15][i >> 4] = A[(m0 + (i >> 4)) * K + k0 + (i & 15)];
            }
            #pragma unroll
            for (int t = 0; t < 4; ++t) {
                int i = tid + t * 256;
                Bs[i >> 6][i & 63] = B[(k0 + (i >> 6)) * N + n0 + (i & 63)];
            }
            __syncthreads();
            #pragma unroll
            for (int kk = 0; kk < 16; ++kk) {
                float2 av = *(const float2*)&As[kk][ty * 2];
                ulonglong2 bv = *(const ulonglong2*)&Bs[kk][tx * 4];
                ull a0 = pk2(av.x, av.x);
                ull a1 = pk2(av.y, av.y);
                acc[0][0] = fma2(a0, bv.x, acc[0][0]);
                acc[0][1] = fma2(a0, bv.y, acc[0][1]);
                acc[1][0] = fma2(a1, bv.x, acc[1][0]);
                acc[1][1] = fma2(a1, bv.y, acc[1][1]);
            }
            __syncthreads();
        }
    }

    int n = n0 + tx * 4;
    float b0 = 0.f, b1 = 0.f, b2 = 0.f, b3 = 0.f;
    if (add_bias) { b0 = bias[n]; b1 = bias[n+1]; b2 = bias[n+2]; b3 = bias[n+3]; }
    #pragma unroll
    for (int r = 0; r < 2; ++r) {
        int m = m0 + ty * 2 + r;
        float2 lo = upk(acc[r][0]);
        float2 hi = upk(acc[r][1]);
        float4 o = make_float4(lo.x + b0, lo.y + b1, hi.x + b2, hi.y + b3);
        *(float4*)&C[m * N + n] = o;
    }
}

__global__ void __launch_bounds__(256) phase1_kernel(
    const float* __restrict__ x,     const float* __restrict__ kernel,
    const float* __restrict__ h_tm1, const float* __restrict__ rec,
    const float* __restrict__ bias,  const float* __restrict__ w,
    const float* __restrict__ hebb,
    float* __restrict__ pre, float* __restrict__ hw, float* __restrict__ red16)
{
    __shared__ __align__(16) float smem[1536];   // 6KB
    int bid = blockIdx.x;
    int tid = threadIdx.x;

    if (bid < 256) {
        int n0 = (bid & 31) * 64;
        int m0 = (bid >> 5) * 32;
        bool do_rec = !(n0 >= 2 * Udim && n0 < 3 * Udim);  // c-slice: no rec
        gemm32x64(x, kernel, h_tm1, rec, bias, pre, N4U, m0, n0, do_rec, true, smem);
    } else if (bid < 320) {
        int t  = bid - 256;
        int n0 = (t & 7) * 64;
        int m0 = (t >> 3) * 32;
        gemm32x64(h_tm1, w, nullptr, nullptr, nullptr, hw, Udim, m0, n0, false, false, smem);
    } else {
        // ---- hebb partial reduce, update-kernel-shaped ----
        // block: (b, 32-u chunk). thread: one v4 column, 16 u's,
        // 4 batches x 4 fully independent LDG.128.
        int t     = bid - 320;       // 0..4095
        int b     = t >> 4;
        int chunk = t & 15;          // 32-u chunk
        int v4    = tid & 127;       // f4 column (512 floats = 128 f4)
        int uh    = tid >> 7;        // 0/1: 16-u half

        ull* hs2 = (ull*)smem;       // 32 duplicated h values
        if (tid < 32) {
            float hv = h_tm1[b * Udim + chunk * 32 + tid];
            hs2[tid] = pk2(hv, hv);
        }
        __syncthreads();

        const float4* p = (const float4*)(hebb
            + (size_t)b * Udim * Udim
            + (size_t)(chunk * 32 + uh * 16) * Udim) + v4;
        const ull* hb = hs2 + uh * 16;

        ull a0x = 0, a0y = 0, a1x = 0, a1y = 0;
        ull a2x = 0, a2y = 0, a3x = 0, a3y = 0;
        #pragma unroll
        for (int k = 0; k < 4; ++k) {
            // 4 independent loads, 4 independent accumulator chains
            float4 l0 = __ldcs(p + (size_t)(k * 4 + 0) * 128);
            float4 l1 = __ldcs(p + (size_t)(k * 4 + 1) * 128);
            float4 l2 = __ldcs(p + (size_t)(k * 4 + 2) * 128);
            float4 l3 = __ldcs(p + (size_t)(k * 4 + 3) * 128);
            ull h0 = hb[k * 4 + 0], h1 = hb[k * 4 + 1];
            ull h2 = hb[k * 4 + 2], h3 = hb[k * 4 + 3];
            ulonglong2 v0 = *(ulonglong2*)&l0;
            ulonglong2 v1 = *(ulonglong2*)&l1;
            ulonglong2 v2 = *(ulonglong2*)&l2;
            ulonglong2 v3 = *(ulonglong2*)&l3;
            a0x = fma2(h0, v0.x, a0x);  a0y = fma2(h0, v0.y, a0y);
            a1x = fma2(h1, v1.x, a1x);  a1y = fma2(h1, v1.y, a1y);
            a2x = fma2(h2, v2.x, a2x);  a2y = fma2(h2, v2.y, a2y);
            a3x = fma2(h3, v3.x, a3x);  a3y = fma2(h3, v3.y, a3y);
        }
        float2 s0 = upk(a0x), s1 = upk(a1x), s2 = upk(a2x), s3 = upk(a3x);
        float2 t0 = upk(a0y), t1 = upk(a1y), t2 = upk(a2y), t3 = upk(a3y);
        float4 acc = make_float4((s0.x + s1.x) + (s2.x + s3.x),
                                 (s0.y + s1.y) + (s2.y + s3.y),
                                 (t0.x + t1.x) + (t2.x + t3.x),
                                 (t0.y + t1.y) + (t2.y + t3.y));

        __syncthreads();
        float4* st = (float4*)(smem + 256);
        if (uh == 1) st[v4] = acc;
        __syncthreads();
        if (uh == 0) {
            float4 o = st[v4];
            acc.x += o.x; acc.y += o.y; acc.z += o.z; acc.w += o.w;
            ((float4*)(red16 + (size_t)(b * 16 + chunk) * Udim))[v4] = acc;
        }
    }
}

// =======================================================================
// Phase 2: combine — gates, c, h, eta reduction, g   (256 blocks x 512)
// =======================================================================
__device__ __forceinline__ float hsig(float z) {
    return fminf(fmaxf(0.2f * z + 0.5f, 0.f), 1.f);
}

__global__ void __launch_bounds__(512) combine_kernel(
    const float* __restrict__ pre, const float* __restrict__ hw,
    const float* __restrict__ red16, const float* __restrict__ c_tm1,
    const float* __restrict__ alpha, const float* __restrict__ h2mod,
    const float* __restrict__ fanout,
    float* __restrict__ out, float* __restrict__ g)
{
    int b = blockIdx.x;
    int v = threadIdx.x;

    const float* r = red16 + (size_t)b * 16 * Udim;
    float red = 0.f;
    #pragma unroll
    for (int j = 0; j < 16; j += 4) {
        float p0 = r[j * Udim + v]       + r[(j + 1) * Udim + v];
        float p1 = r[(j + 2) * Udim + v] + r[(j + 3) * Udim + v];
        red += p0 + p1;
    }

    float xi = pre[b * N4U + v];
    float xf = pre[b * N4U + Udim + v];
    float xc = pre[b * N4U + 2 * Udim + v];
    float xo = pre[b * N4U + 3 * Udim + v];

    float gi = hsig(xi), gf = hsig(xf), go = hsig(xo);
    float itc = tanhf(xc + hw[b * Udim + v] + alpha[v] * red);
    float c = gf * c_tm1[b * Udim + v] + gi * itc;
    float h = go * tanhf(c);

    out[b * Udim + v] = h;
    out[Bdim * Udim + b * Udim + v] = c;

    float s = h * h2mod[v];
    #pragma unroll
    for (int o = 16; o > 0; o >>= 1) s += __shfl_down_sync(0xffffffffu, s, o);
    __shared__ float ws[16];
    __shared__ float eta_s;
    if ((v & 31) == 0) ws[v >> 5] = s;
    __syncthreads();
    if (v < 16) {
        float t = ws[v];
        #pragma unroll
        for (int o = 8; o > 0; o >>= 1) t += __shfl_down_sync(0xffffu, t, o);
        if (v == 0) eta_s = tanhf(t);
    }
    __syncthreads();
    g[b * Udim + v] = eta_s * fanout[v] * itc;
}

// =======================================================================
// Phase 3: hebb update — 4 independent float4 per thread, streaming hints
// =======================================================================
__global__ void __launch_bounds__(256) hebb_update(
    const float* __restrict__ hebb, const float* __restrict__ h_tm1,
    const float* __restrict__ g, float* __restrict__ out)
{
    int base = blockIdx.x * 1024 + threadIdx.x;

    #pragma unroll
    for (int k = 0; k < 4; ++k) {
        int idx = base + k * 256;
        int row = idx >> 7;            // b*512 + u
        int v4  = idx & 127;
        int b   = idx >> 16;

        float hu = h_tm1[row];
        float4 hv = __ldcs(((const float4*)hebb) + idx);
        float4 gg = ((const float4*)(g + b * Udim))[v4];

        float4 r;
        r.x = fminf(fmaxf(hv.x + hu * gg.x, -2.f), 2.f);
        r.y = fminf(fmaxf(hv.y + hu * gg.y, -2.f), 2.f);
        r.z = fminf(fmaxf(hv.z + hu * gg.z, -2.f), 2.f);
        r.w = fminf(fmaxf(hv.w + hu * gg.w, -2.f), 2.f);
        __stcs(((float4*)out) + idx, r);
    }
}

// ---------------- launch ----------------
extern "C" void kernel_launch(void* const* d_in, const int* in_sizes, int n_in,
                              void* d_out, int out_size)
{
    const float* x      = (const float*)d_in[0];
    const float* h_tm1  = (const float*)d_in[1];
    const float* c_tm1  = (const float*)d_in[2];
    const float* hebb   = (const float*)d_in[3];
    const float* kernel = (const float*)d_in[4];
    const float* rec    = (const float*)d_in[5];
    const float* bias   = (const float*)d_in[6];
    const float* w      = (const float*)d_in[7];
    const float* alpha  = (const float*)d_in[8];
    const float* h2mod  = (const float*)d_in[9];
    const float* fanout = (const float*)d_in[10];
    float* out = (float*)d_out;

    float *pre, *hw, *red16, *gg;
    cudaGetSymbolAddress((void**)&pre,   g_pre);
    cudaGetSymbolAddress((void**)&hw,    g_hw);
    cudaGetSymbolAddress((void**)&red16, g_red16);
    cudaGetSymbolAddress((void**)&gg,    g_g);

    phase1_kernel<<<320 + 4096, 256>>>(x, kernel, h_tm1, rec, bias, w, hebb,
                                       pre, hw, red16);
    combine_kernel<<<Bdim, Udim>>>(pre, hw, red16, c_tm1, alpha, h2mod, fanout, out, gg);
    hebb_update<<<16384, 256>>>(hebb, h_tm1, gg, out + 2 * Bdim * Udim);
}